// round 8
// baseline (speedup 1.0000x reference)
#include <cuda_runtime.h>
#include <cuda_bf16.h>
#include <cstdint>

#define S_DIM 51
#define B_DIM 2048
#define H_DIM 1024
#define OUT_DIM 904
#define M_DIM (S_DIM * B_DIM)   /* 104448 */
#define NARG (M_DIM * 6)
#define N_PAD 1024
#define NEG_BIG (-1.0e30f)
#define MARGIN 2.5e-3f

#define BMT 128
#define BNT 128
#define KC 32
#define NCH (H_DIM / KC)
#define SPL_BYTES 8192
#define B_OFF 24576
#define BUF_BYTES 49152
#define SMEM_TOTAL (2 * BUF_BYTES)

__device__ float g_fc[(size_t)M_DIM * OUT_DIM];
__device__ __nv_bfloat16 gB0[N_PAD * H_DIM], gB1[N_PAD * H_DIM], gB2[N_PAD * H_DIM];
__device__ int g_ccnt, g_mcnt;
__device__ int g_clist[M_DIM];
__device__ int g_mlist[NARG];

// ---------------- PTX helpers (sm_80-class; no tcgen05 on compute_103) ----------------
__device__ __forceinline__ void ldsm4(uint32_t a[4], uint32_t addr) {
    asm volatile("ldmatrix.sync.aligned.m8n8.x4.shared.b16 {%0,%1,%2,%3}, [%4];"
                 : "=r"(a[0]), "=r"(a[1]), "=r"(a[2]), "=r"(a[3]) : "r"(addr));
}
__device__ __forceinline__ void mma16816(float c[4], const uint32_t a[4], const uint32_t b[2]) {
    asm volatile("mma.sync.aligned.m16n8k16.row.col.f32.bf16.bf16.f32 "
                 "{%0,%1,%2,%3}, {%4,%5,%6,%7}, {%8,%9}, {%0,%1,%2,%3};"
                 : "+f"(c[0]), "+f"(c[1]), "+f"(c[2]), "+f"(c[3])
                 : "r"(a[0]), "r"(a[1]), "r"(a[2]), "r"(a[3]), "r"(b[0]), "r"(b[1]));
}
#define CP_ASYNC16(dst, src) \
    asm volatile("cp.async.cg.shared.global [%0], [%1], 16;" :: "r"(dst), "l"(src) : "memory")
#define CP_COMMIT() asm volatile("cp.async.commit_group;" ::: "memory")
#define CP_WAIT0() asm volatile("cp.async.wait_group 0;" ::: "memory")

// ---------------- Threefry / sampling helpers (proven exact R4) ----------------
__device__ __forceinline__ uint2 tf2x32(uint32_t k0, uint32_t k1, uint32_t c0, uint32_t c1) {
    uint32_t ks2 = k0 ^ k1 ^ 0x1BD11BDAu;
    uint32_t x0 = c0 + k0, x1 = c1 + k1;
    uint32_t ks[3] = {k0, k1, ks2};
    const int RA[4] = {13, 15, 26, 6};
    const int RB[4] = {17, 29, 16, 24};
#pragma unroll
    for (int blk = 0; blk < 5; blk++) {
        const int* rr = (blk & 1) ? RB : RA;
#pragma unroll
        for (int i = 0; i < 4; i++) { x0 += x1; x1 = __funnelshift_l(x1, x1, rr[i]); x1 ^= x0; }
        x0 += ks[(blk + 1) % 3];
        x1 += ks[(blk + 2) % 3] + (uint32_t)(blk + 1);
    }
    return make_uint2(x0, x1);
}
__device__ __forceinline__ uint32_t rand32(uint32_t k0, uint32_t k1, uint32_t idx) {
    uint2 r = tf2x32(k0, k1, 0u, idx);
    return r.x ^ r.y;
}
__device__ __forceinline__ float gumbel_u32(uint32_t bits) {
    float f = __uint_as_float((bits >> 9) | 0x3f800000u) - 1.0f;
    float u = fmaxf(f, 1.17549435e-38f);
    return -logf(-logf(u));
}
__device__ __forceinline__ float normal_u32(uint32_t bits) {
    float f = __uint_as_float((bits >> 9) | 0x3f800000u) - 1.0f;
    const float lo = -0.99999994f;
    float u = fmaxf(f * 2.0f + lo, lo);
    return 1.41421356237f * erfinvf(u);
}

__global__ void zero_counters() { g_ccnt = 0; g_mcnt = 0; }

// ---------------- W split fp32 -> 3x bf16 (padded rows zero) ----------------
__global__ void split_W(const float* __restrict__ W) {
    int i = blockIdx.x * blockDim.x + threadIdx.x;
    if (i >= N_PAD * H_DIM / 4) return;
    int row = i >> 8;
    float4 a = (row < OUT_DIM) ? ((const float4*)W)[i] : make_float4(0.f, 0.f, 0.f, 0.f);
    float v[4] = {a.x, a.y, a.z, a.w};
#pragma unroll
    for (int c = 0; c < 4; c++) {
        __nv_bfloat16 h0 = __float2bfloat16_rn(v[c]);
        float r1 = v[c] - __bfloat162float(h0);
        __nv_bfloat16 h1 = __float2bfloat16_rn(r1);
        float r2 = r1 - __bfloat162float(h1);
        __nv_bfloat16 h2 = __float2bfloat16_rn(r2);
        gB0[i * 4 + c] = h0; gB1[i * 4 + c] = h1; gB2[i * 4 + c] = h2;
    }
}

// ---------------- GEMM loaders ----------------
__device__ __forceinline__ void lda_g(float4 av[4], const float* __restrict__ A,
                                      int m0, int ch, int tid) {
    const int row = tid >> 1, h = tid & 1;
    const float4* p = (const float4*)(A + (size_t)(m0 + row) * H_DIM + ch * KC + h * 16);
#pragma unroll
    for (int j = 0; j < 4; j++) av[j] = p[j];
}

__device__ __forceinline__ void sta_s(char* sm, int buf, const float4 av[4], int tid) {
    const int row = tid >> 1, h = tid & 1;
    float v[16];
#pragma unroll
    for (int j = 0; j < 4; j++) {
        v[j * 4 + 0] = av[j].x; v[j * 4 + 1] = av[j].y;
        v[j * 4 + 2] = av[j].z; v[j * 4 + 3] = av[j].w;
    }
    uint32_t p0[8], p1[8], p2[8];
#pragma unroll
    for (int e = 0; e < 8; e++) {
        uint32_t w0 = 0, w1 = 0, w2 = 0;
#pragma unroll
        for (int half = 0; half < 2; half++) {
            float x = v[e * 2 + half];
            __nv_bfloat16 h0 = __float2bfloat16_rn(x);
            float r1 = x - __bfloat162float(h0);
            __nv_bfloat16 h1 = __float2bfloat16_rn(r1);
            float r2 = r1 - __bfloat162float(h1);
            __nv_bfloat16 h2 = __float2bfloat16_rn(r2);
            w0 |= (uint32_t)(*(uint16_t*)&h0) << (16 * half);
            w1 |= (uint32_t)(*(uint16_t*)&h1) << (16 * half);
            w2 |= (uint32_t)(*(uint16_t*)&h2) << (16 * half);
        }
        p0[e] = w0; p1[e] = w1; p2[e] = w2;
    }
    char* base = sm + buf * BUF_BYTES + row * 64;
    const int xr = ((row >> 1) & 3) << 4;
    const int swlo = (((h * 2 + 0) << 4) ^ xr);
    const int swhi = (((h * 2 + 1) << 4) ^ xr);
    *(uint4*)(base + 0 * SPL_BYTES + swlo) = make_uint4(p0[0], p0[1], p0[2], p0[3]);
    *(uint4*)(base + 0 * SPL_BYTES + swhi) = make_uint4(p0[4], p0[5], p0[6], p0[7]);
    *(uint4*)(base + 1 * SPL_BYTES + swlo) = make_uint4(p1[0], p1[1], p1[2], p1[3]);
    *(uint4*)(base + 1 * SPL_BYTES + swhi) = make_uint4(p1[4], p1[5], p1[6], p1[7]);
    *(uint4*)(base + 2 * SPL_BYTES + swlo) = make_uint4(p2[0], p2[1], p2[2], p2[3]);
    *(uint4*)(base + 2 * SPL_BYTES + swhi) = make_uint4(p2[4], p2[5], p2[6], p2[7]);
}

__device__ __forceinline__ void ldb_cp(uint32_t sbase, int buf, int n0, int ch, int tid) {
    const __nv_bfloat16* gb[3] = {gB0, gB1, gB2};
#pragma unroll
    for (int t = 0; t < 6; t++) {
        const int u = tid + t * 256;
        const int s = u >> 9;
        const int rem = u & 511;
        const int row = rem >> 2, q = rem & 3;
        const void* src = gb[s] + (size_t)(n0 + row) * H_DIM + ch * KC + q * 8;
        const uint32_t dst = sbase + buf * BUF_BYTES + B_OFF + s * SPL_BYTES +
                             row * 64 + ((q << 4) ^ (((row >> 1) & 3) << 4));
        CP_ASYNC16(dst, src);
    }
}

// ---------------- GEMM: g_fc[M,904] = A * W^T + b  (bf16x6, mma.sync) ----------------
__global__ __launch_bounds__(256, 1)
void gemm_mma(const float* __restrict__ A, const float* __restrict__ bias) {
    extern __shared__ char sm[];
    const uint32_t sbase = (uint32_t)__cvta_generic_to_shared(sm);
    const int tid = threadIdx.x;
    const int lane = tid & 31, warp = tid >> 5;
    const int wm0 = (warp & 1) * 64;
    const int wn0 = (warp >> 1) * 32;
    const int n0 = blockIdx.x * BNT;
    const int m0 = blockIdx.y * BMT;

    const int lg = lane >> 3, lr = lane & 7;
    const int akc = lg >> 1;
    const int bkc = lg & 1;
    int aoff[4], axor[4];
#pragma unroll
    for (int mt = 0; mt < 4; mt++) {
        const int r = wm0 + mt * 16 + ((lg & 1) << 3) + lr;
        aoff[mt] = r * 64;
        axor[mt] = ((r >> 1) & 3) << 4;
    }
    int boff[2], bxor[2];
#pragma unroll
    for (int bt = 0; bt < 2; bt++) {
        const int r = wn0 + (bt * 2 + (lg >> 1)) * 8 + lr;
        boff[bt] = r * 64;
        bxor[bt] = ((r >> 1) & 3) << 4;
    }

    float c[4][4][4];
#pragma unroll
    for (int i = 0; i < 4; i++)
#pragma unroll
        for (int j = 0; j < 4; j++)
#pragma unroll
            for (int e = 0; e < 4; e++) c[i][j][e] = 0.0f;

    float4 av[4];
    lda_g(av, A, m0, 0, tid);
    ldb_cp(sbase, 0, n0, 0, tid);
    CP_COMMIT();
    sta_s(sm, 0, av, tid);
    CP_WAIT0();
    __syncthreads();

    for (int ch = 0; ch < NCH; ch++) {
        const int buf = ch & 1;
        const bool pf = (ch + 1) < NCH;
        if (pf) {
            lda_g(av, A, m0, ch + 1, tid);
            ldb_cp(sbase, buf ^ 1, n0, ch + 1, tid);
            CP_COMMIT();
        }

        const uint32_t Ab = sbase + buf * BUF_BYTES;
        const uint32_t Bb = Ab + B_OFF;
#pragma unroll
        for (int kt = 0; kt < 2; kt++) {
            uint32_t bf[3][4][2];
#pragma unroll
            for (int s = 0; s < 3; s++)
#pragma unroll
                for (int bt = 0; bt < 2; bt++) {
                    uint32_t r[4];
                    ldsm4(r, Bb + s * SPL_BYTES + boff[bt] +
                              ((((kt << 1) + bkc) << 4) ^ bxor[bt]));
                    bf[s][bt * 2][0] = r[0]; bf[s][bt * 2][1] = r[1];
                    bf[s][bt * 2 + 1][0] = r[2]; bf[s][bt * 2 + 1][1] = r[3];
                }
#pragma unroll
            for (int S = 0; S < 3; S++) {
                uint32_t af[4][4];
#pragma unroll
                for (int mt = 0; mt < 4; mt++)
                    ldsm4(af[mt], Ab + S * SPL_BYTES + aoff[mt] +
                                  ((((kt << 1) + akc) << 4) ^ axor[mt]));
#pragma unroll
                for (int T = 0; T < 3 - S; T++)
#pragma unroll
                    for (int mt = 0; mt < 4; mt++)
#pragma unroll
                        for (int nt = 0; nt < 4; nt++)
                            mma16816(c[mt][nt], af[mt], bf[T][nt]);
            }
        }

        if (pf) sta_s(sm, buf ^ 1, av, tid);
        CP_WAIT0();
        __syncthreads();
    }

#pragma unroll
    for (int mt = 0; mt < 4; mt++) {
#pragma unroll
        for (int nt = 0; nt < 4; nt++) {
            const int col = n0 + wn0 + nt * 8 + ((lane & 3) << 1);
            if (col < OUT_DIM) {
                const float bx = bias[col], by = bias[col + 1];
                const int r0 = m0 + wm0 + mt * 16 + (lane >> 2);
                *(float2*)(g_fc + (size_t)r0 * OUT_DIM + col) =
                    make_float2(c[mt][nt][0] + bx, c[mt][nt][1] + by);
                *(float2*)(g_fc + (size_t)(r0 + 8) * OUT_DIM + col) =
                    make_float2(c[mt][nt][2] + bx, c[mt][nt][3] + by);
            }
        }
    }
}

// ---------------- command: fast path or push to worklist ----------------
__global__ void command_kernel(float* __restrict__ out) {
    const int row = blockIdx.x * blockDim.x + threadIdx.x;
    if (row >= M_DIM) return;
    const float4 x4 = *(const float4*)(g_fc + (size_t)row * OUT_DIM);
    float x[4] = {x4.x, x4.y, x4.z, x4.w};

    int best = 0; float m = x[0];
#pragma unroll
    for (int c = 1; c < 4; c++) if (x[c] > m) { m = x[c]; best = c; }
    int nnear = 0;
#pragma unroll
    for (int c = 0; c < 4; c++) nnear += (x[c] > m - MARGIN) ? 1 : 0;

    if (nnear > 1) {
        int slot = atomicAdd(&g_ccnt, 1);
        g_clist[slot] = row;        // fixup writes the one-hot
        return;
    }
    float2* o = (float2*)(out + (size_t)row * 10);
    o[0] = make_float2(best == 0 ? 1.f : 0.f, best == 1 ? 1.f : 0.f);
    o[1] = make_float2(best == 2 ? 1.f : 0.f, best == 3 ? 1.f : 0.f);
}

// ---------------- mixture: fast path or push to worklist ----------------
__global__ void mixture_kernel(float* __restrict__ out,
                               uint32_t kg0, uint32_t kg1) {
    const int gwarp = (blockIdx.x * blockDim.x + threadIdx.x) >> 5;
    const int lane = threadIdx.x & 31;
    if (gwarp >= NARG) return;

    const int sbr = gwarp / 6;
    const int j = gwarp - sbr * 6;
    const float* base = g_fc + (size_t)sbr * OUT_DIM + 4 + j * 150;

    const float x0 = base[lane];
    const float x1 = (lane < 18) ? base[32 + lane] : NEG_BIG;

    float m = fmaxf(x0, x1);
#pragma unroll
    for (int o = 16; o; o >>= 1) m = fmaxf(m, __shfl_xor_sync(0xffffffffu, m, o));

    const float th = m - MARGIN;
    const unsigned f0 = __ballot_sync(0xffffffffu, x0 > th);
    const unsigned f1 = __ballot_sync(0xffffffffu, x1 > th);

    if (__popc(f0) + __popc(f1) != 1) {
        if (lane == 0) {
            int slot = atomicAdd(&g_mcnt, 1);
            g_mlist[slot] = gwarp;   // fixup writes the arg
        }
        return;
    }
    const int k = f0 ? (__ffs(f0) - 1) : (31 + __ffs(f1));
    if (lane == 0) {
        const float mean = base[50 + k];
        const float lstd = base[100 + k];
        const float n = normal_u32(rand32(kg0, kg1, (uint32_t)gwarp));
        out[(size_t)sbr * 10 + 4 + j] = mean + expf(lstd) * (n * 0.01f);
    }
}

// ---------------- cmd fixup: exact sequential-fp32 recompute, 1 warp/entry ----------------
__global__ void cmd_fixup(const float* __restrict__ A, const float* __restrict__ W,
                          const float* __restrict__ bias, float* __restrict__ out,
                          uint32_t kc0, uint32_t kc1) {
    const int nwarp = (gridDim.x * blockDim.x) >> 5;
    const int lane = threadIdx.x & 31;
    for (int e = (blockIdx.x * blockDim.x + threadIdx.x) >> 5; e < g_ccnt; e += nwarp) {
        const int row = g_clist[e];
        float sc = NEG_BIG;
        if (lane < 4) {
            const float* a = A + (size_t)row * H_DIM;
            const float* w = W + (size_t)lane * H_DIM;
            float acc = 0.0f;
            for (int k = 0; k < H_DIM; k++) acc = fmaf(a[k], w[k], acc);
            const float x = acc + bias[lane];
            sc = gumbel_u32(rand32(kc0, kc1, (uint32_t)(row * 4 + lane))) +
                 __fdiv_rn(x, 1e-4f);
        }
        // argmax over 4 lanes, first index wins on exact ties
        int bi = lane;
#pragma unroll
        for (int o = 1; o < 4; o <<= 1) {
            float os = __shfl_xor_sync(0xffffffffu, sc, o);
            int oi = __shfl_xor_sync(0xffffffffu, bi, o);
            if (os > sc || (os == sc && oi < bi)) { sc = os; bi = oi; }
        }
        if (lane == 0) {
            float2* o2 = (float2*)(out + (size_t)row * 10);
            o2[0] = make_float2(bi == 0 ? 1.f : 0.f, bi == 1 ? 1.f : 0.f);
            o2[1] = make_float2(bi == 2 ? 1.f : 0.f, bi == 3 ? 1.f : 0.f);
        }
    }
}

// ---------------- mix fixup: recompute all 50 logits sequentially, 1 block/entry ----------------
__global__ __launch_bounds__(64)
void mix_fixup(const float* __restrict__ A, const float* __restrict__ W,
               const float* __restrict__ bias, float* __restrict__ out,
               uint32_t km0, uint32_t km1, uint32_t kg0, uint32_t kg1) {
    __shared__ float sa[H_DIM];
    __shared__ float sx[50];
    for (int e = blockIdx.x; e < g_mcnt; e += gridDim.x) {
        const int gw = g_mlist[e];
        const int sbr = gw / 6;
        const int j = gw - sbr * 6;
        __syncthreads();   // protect sa/sx reuse across loop iterations
        {
            const float4* src = (const float4*)(A + (size_t)sbr * H_DIM);
            float4* dst = (float4*)sa;
            for (int i = threadIdx.x; i < H_DIM / 4; i += 64) dst[i] = src[i];
        }
        __syncthreads();
        const int c = threadIdx.x;
        if (c < 50) {
            const int col = 4 + j * 150 + c;
            const float* w = W + (size_t)col * H_DIM;
            float acc = 0.0f;
            for (int k = 0; k < H_DIM; k++) acc = fmaf(sa[k], w[k], acc);
            sx[c] = acc + bias[col];
        }
        __syncthreads();
        if (threadIdx.x == 0) {
            float m = sx[0];
            for (int i = 1; i < 50; i++) m = fmaxf(m, sx[i]);
            float s = 0.0f;
            for (int i = 0; i < 50; i++) s += expf(sx[i] - m);
            const float lse = logf(s) + m;
            float bsc = NEG_BIG; int bk = 0;
            const uint32_t eb = (uint32_t)gw * 50u;
            for (int i = 0; i < 50; i++) {
                const float g = gumbel_u32(rand32(km0, km1, eb + (uint32_t)i));
                const float sc = g + __fdiv_rn(sx[i] - lse, 1e-4f);
                if (sc > bsc) { bsc = sc; bk = i; }
            }
            const float* base = g_fc + (size_t)sbr * OUT_DIM + 4 + j * 150;
            const float mean = base[50 + bk];
            const float lstd = base[100 + bk];
            const float n = normal_u32(rand32(kg0, kg1, (uint32_t)gw));
            out[(size_t)sbr * 10 + 4 + j] = mean + expf(lstd) * (n * 0.01f);
        }
    }
}

// ---------------- host threefry ----------------
static inline uint32_t h_rotl(uint32_t v, int r) { return (v << r) | (v >> (32 - r)); }
static void h_tf(uint32_t k0, uint32_t k1, uint32_t c0, uint32_t c1,
                 uint32_t* o0, uint32_t* o1) {
    uint32_t ks2 = k0 ^ k1 ^ 0x1BD11BDAu;
    uint32_t x0 = c0 + k0, x1 = c1 + k1;
    uint32_t ks[3] = {k0, k1, ks2};
    const int RA[4] = {13, 15, 26, 6};
    const int RB[4] = {17, 29, 16, 24};
    for (int blk = 0; blk < 5; blk++) {
        const int* rr = (blk & 1) ? RB : RA;
        for (int i = 0; i < 4; i++) { x0 += x1; x1 = h_rotl(x1, rr[i]); x1 ^= x0; }
        x0 += ks[(blk + 1) % 3];
        x1 += ks[(blk + 2) % 3] + (uint32_t)(blk + 1);
    }
    *o0 = x0; *o1 = x1;
}

extern "C" void kernel_launch(void* const* d_in, const int* in_sizes, int n_in,
                              void* d_out, int out_size) {
    const float* A = (const float*)d_in[0];
    const float* W = (const float*)d_in[1];
    const float* b = (const float*)d_in[2];
    float* out = (float*)d_out;

    uint32_t kc0, kc1, km0, km1, kg0, kg1;
    h_tf(0u, 42u, 0u, 0u, &kc0, &kc1);
    h_tf(0u, 42u, 0u, 1u, &km0, &km1);
    h_tf(0u, 42u, 0u, 2u, &kg0, &kg1);

    cudaFuncSetAttribute(gemm_mma, cudaFuncAttributeMaxDynamicSharedMemorySize, SMEM_TOTAL);

    zero_counters<<<1, 1>>>();
    split_W<<<(N_PAD * H_DIM / 4 + 255) / 256, 256>>>(W);
    gemm_mma<<<dim3(N_PAD / BNT, M_DIM / BMT), 256, SMEM_TOTAL>>>(A, b);
    command_kernel<<<(M_DIM + 255) / 256, 256>>>(out);

    const int mwpb = 8;
    mixture_kernel<<<(NARG + mwpb - 1) / mwpb, mwpb * 32>>>(out, kg0, kg1);

    cmd_fixup<<<1024, 256>>>(A, W, b, out, kc0, kc1);
    mix_fixup<<<8192, 64>>>(A, W, b, out, km0, km1, kg0, kg1);
}

// round 10
// speedup vs baseline: 1.5414x; 1.5414x over previous
#include <cuda_runtime.h>
#include <cstdint>

#define S_DIM 51
#define B_DIM 2048
#define H_DIM 1024
#define OUT_DIM 904
#define NC 320                  /* compact cols: 4 cmd + 300 logmix + 16 pad */
#define M_DIM (S_DIM * B_DIM)   /* 104448 */
#define NARG (M_DIM * 6)
#define NEG_BIG (-1.0e30f)
#define MARGIN 2.5e-3f

__device__ float g_fc2[(size_t)M_DIM * NC];     /* 133.7 MB */
__device__ float gWc[NC * H_DIM];
__device__ float g_bc[NC];
__device__ int g_karr[NARG];
__device__ int g_ccnt, g_mcnt;
__device__ int g_clist[M_DIM];
__device__ int g_mlist[NARG];

// ---------------- Threefry / sampling helpers (proven exact R4/R8) ----------------
__device__ __forceinline__ uint2 tf2x32(uint32_t k0, uint32_t k1, uint32_t c0, uint32_t c1) {
    uint32_t ks2 = k0 ^ k1 ^ 0x1BD11BDAu;
    uint32_t x0 = c0 + k0, x1 = c1 + k1;
    uint32_t ks[3] = {k0, k1, ks2};
    const int RA[4] = {13, 15, 26, 6};
    const int RB[4] = {17, 29, 16, 24};
#pragma unroll
    for (int blk = 0; blk < 5; blk++) {
        const int* rr = (blk & 1) ? RB : RA;
#pragma unroll
        for (int i = 0; i < 4; i++) { x0 += x1; x1 = __funnelshift_l(x1, x1, rr[i]); x1 ^= x0; }
        x0 += ks[(blk + 1) % 3];
        x1 += ks[(blk + 2) % 3] + (uint32_t)(blk + 1);
    }
    return make_uint2(x0, x1);
}
__device__ __forceinline__ uint32_t rand32(uint32_t k0, uint32_t k1, uint32_t idx) {
    uint2 r = tf2x32(k0, k1, 0u, idx);
    return r.x ^ r.y;
}
__device__ __forceinline__ float gumbel_u32(uint32_t bits) {
    float f = __uint_as_float((bits >> 9) | 0x3f800000u) - 1.0f;
    float u = fmaxf(f, 1.17549435e-38f);
    return -logf(-logf(u));
}
__device__ __forceinline__ float normal_u32(uint32_t bits) {
    float f = __uint_as_float((bits >> 9) | 0x3f800000u) - 1.0f;
    const float lo = -0.99999994f;
    float u = fmaxf(f * 2.0f + lo, lo);
    return 1.41421356237f * erfinvf(u);
}

__global__ void zero_counters() { g_ccnt = 0; g_mcnt = 0; }

// ---------------- compact W: rows {0..3} + {4+j*150+c : j<6, c<50}, pad zeros ----------------
__global__ void build_Wc(const float* __restrict__ W, const float* __restrict__ bias) {
    int i = blockIdx.x * blockDim.x + threadIdx.x;      // over NC*H/4 float4s
    if (i >= NC * H_DIM / 4) return;
    const int row = i >> 8;                             // 256 float4 per row
    int src;
    if (row < 4) src = row;
    else if (row < 304) { const int t = row - 4; src = 4 + (t / 50) * 150 + (t % 50); }
    else src = -1;
    ((float4*)gWc)[i] = (src >= 0)
        ? ((const float4*)W)[(size_t)src * (H_DIM / 4) + (i & 255)]
        : make_float4(0.f, 0.f, 0.f, 0.f);
    if ((i & 255) == 0) g_bc[row] = (src >= 0) ? bias[src] : 0.0f;
}

// ---------------- GEMM (R4-identical chain): g_fc2[M,320] = A * Wc^T + bc ----------------
#define BM 128
#define BN 64
#define BK 16

__global__ __launch_bounds__(256)
void gemm_kernel(const float* __restrict__ A) {
    __shared__ float As[BK][BM + 4];
    __shared__ float Bs[BK][BN + 4];

    const int tid = threadIdx.x;
    const int tx = tid & 15;
    const int ty = tid >> 4;
    const int row0 = blockIdx.y * BM;
    const int col0 = blockIdx.x * BN;

    float acc[8][4];
#pragma unroll
    for (int i = 0; i < 8; i++)
#pragma unroll
        for (int j = 0; j < 4; j++) acc[i][j] = 0.0f;

    const int ar0 = tid >> 2, ar1 = ar0 + 64;
    const int ak = (tid & 3) << 2;
    const int br = tid >> 2;
    const int bk = (tid & 3) << 2;

    const float* Ap0 = A + (size_t)(row0 + ar0) * H_DIM + ak;
    const float* Ap1 = A + (size_t)(row0 + ar1) * H_DIM + ak;
    const float* Wp  = gWc + (size_t)(col0 + br) * H_DIM + bk;

    float4 pa0 = *(const float4*)Ap0;
    float4 pa1 = *(const float4*)Ap1;
    float4 pb = *(const float4*)Wp;

    for (int k0 = 0; k0 < H_DIM; k0 += BK) {
        As[ak + 0][ar0] = pa0.x; As[ak + 1][ar0] = pa0.y;
        As[ak + 2][ar0] = pa0.z; As[ak + 3][ar0] = pa0.w;
        As[ak + 0][ar1] = pa1.x; As[ak + 1][ar1] = pa1.y;
        As[ak + 2][ar1] = pa1.z; As[ak + 3][ar1] = pa1.w;
        Bs[bk + 0][br] = pb.x; Bs[bk + 1][br] = pb.y;
        Bs[bk + 2][br] = pb.z; Bs[bk + 3][br] = pb.w;
        __syncthreads();

        const int kn = k0 + BK;
        if (kn < H_DIM) {
            pa0 = *(const float4*)(Ap0 + kn);
            pa1 = *(const float4*)(Ap1 + kn);
            pb = *(const float4*)(Wp + kn);
        }

#pragma unroll
        for (int k = 0; k < BK; k++) {
            float4 a0 = *(const float4*)(&As[k][ty * 8]);
            float4 a1 = *(const float4*)(&As[k][ty * 8 + 4]);
            float4 b4 = *(const float4*)(&Bs[k][tx * 4]);
            float av[8] = {a0.x, a0.y, a0.z, a0.w, a1.x, a1.y, a1.z, a1.w};
            float bv[4] = {b4.x, b4.y, b4.z, b4.w};
#pragma unroll
            for (int i = 0; i < 8; i++)
#pragma unroll
                for (int j = 0; j < 4; j++)
                    acc[i][j] = fmaf(av[i], bv[j], acc[i][j]);
        }
        __syncthreads();
    }

    const int c = col0 + tx * 4;
    const float4 bb = *(const float4*)(g_bc + c);
#pragma unroll
    for (int i = 0; i < 8; i++) {
        const int r = row0 + ty * 8 + i;
        float4 o;
        o.x = acc[i][0] + bb.x; o.y = acc[i][1] + bb.y;
        o.z = acc[i][2] + bb.z; o.w = acc[i][3] + bb.w;
        *(float4*)(g_fc2 + (size_t)r * NC + c) = o;
    }
}

// ---------------- command: fast path or push to worklist ----------------
__global__ void command_kernel(float* __restrict__ out) {
    const int row = blockIdx.x * blockDim.x + threadIdx.x;
    if (row >= M_DIM) return;
    const float4 x4 = *(const float4*)(g_fc2 + (size_t)row * NC);
    float x[4] = {x4.x, x4.y, x4.z, x4.w};

    int best = 0; float m = x[0];
#pragma unroll
    for (int c = 1; c < 4; c++) if (x[c] > m) { m = x[c]; best = c; }
    int nnear = 0;
#pragma unroll
    for (int c = 0; c < 4; c++) nnear += (x[c] > m - MARGIN) ? 1 : 0;

    if (nnear > 1) {
        int slot = atomicAdd(&g_ccnt, 1);
        g_clist[slot] = row;
        return;
    }
    float2* o = (float2*)(out + (size_t)row * 10);
    o[0] = make_float2(best == 0 ? 1.f : 0.f, best == 1 ? 1.f : 0.f);
    o[1] = make_float2(best == 2 ? 1.f : 0.f, best == 3 ? 1.f : 0.f);
}

// ---------------- mixture: record winning k (or -1 + worklist) ----------------
__global__ void mixture_kernel() {
    const int gwarp = (blockIdx.x * blockDim.x + threadIdx.x) >> 5;
    const int lane = threadIdx.x & 31;
    if (gwarp >= NARG) return;

    const int sbr = gwarp / 6;
    const int j = gwarp - sbr * 6;
    const float* base = g_fc2 + (size_t)sbr * NC + 4 + j * 50;

    const float x0 = base[lane];
    const float x1 = (lane < 18) ? base[32 + lane] : NEG_BIG;

    float m = fmaxf(x0, x1);
#pragma unroll
    for (int o = 16; o; o >>= 1) m = fmaxf(m, __shfl_xor_sync(0xffffffffu, m, o));

    const float th = m - MARGIN;
    const unsigned f0 = __ballot_sync(0xffffffffu, x0 > th);
    const unsigned f1 = __ballot_sync(0xffffffffu, x1 > th);

    if (lane == 0) {
        if (__popc(f0) + __popc(f1) != 1) {
            g_karr[gwarp] = -1;
            int slot = atomicAdd(&g_mcnt, 1);
            g_mlist[slot] = gwarp;
        } else {
            g_karr[gwarp] = f0 ? (__ffs(f0) - 1) : (31 + __ffs(f1));
        }
    }
}

// ---------------- gather: per row, compute chosen mean/logstd + write args ----------------
__global__ __launch_bounds__(384)
void gather_kernel(const float* __restrict__ A, const float* __restrict__ W,
                   const float* __restrict__ bias, float* __restrict__ out,
                   uint32_t kg0, uint32_t kg1) {
    __shared__ float sa[H_DIM];
    __shared__ float sval[12];
    const int sbr = blockIdx.x;
    const int tid = threadIdx.x;
    const int warp = tid >> 5, lane = tid & 31;

    {
        const float4* src = (const float4*)(A + (size_t)sbr * H_DIM);
        if (tid < 256) ((float4*)sa)[tid] = src[tid];
    }
    __syncthreads();

    const int j = warp >> 1, which = warp & 1;
    const int k = g_karr[sbr * 6 + j];
    if (k >= 0) {
        const int col = 4 + j * 150 + 50 + which * 50 + k;
        const float* w = W + (size_t)col * H_DIM;
        float acc = 0.0f;
#pragma unroll
        for (int t = 0; t < H_DIM / 32; t++)
            acc = fmaf(sa[t * 32 + lane], w[t * 32 + lane], acc);
#pragma unroll
        for (int o = 16; o; o >>= 1) acc += __shfl_xor_sync(0xffffffffu, acc, o);
        if (lane == 0) sval[warp] = acc + bias[col];
    }
    __syncthreads();

    if (tid < 6) {
        const int kk = g_karr[sbr * 6 + tid];
        if (kk >= 0) {
            const float mean = sval[tid * 2];
            const float lstd = sval[tid * 2 + 1];
            const float n = normal_u32(rand32(kg0, kg1, (uint32_t)(sbr * 6 + tid)));
            out[(size_t)sbr * 10 + 4 + tid] = mean + expf(lstd) * (n * 0.01f);
        }
    }
}

// ---------------- cmd fixup: exact sequential recompute (proven R8) ----------------
__global__ void cmd_fixup(const float* __restrict__ A, const float* __restrict__ W,
                          const float* __restrict__ bias, float* __restrict__ out,
                          uint32_t kc0, uint32_t kc1) {
    const int nwarp = (gridDim.x * blockDim.x) >> 5;
    const int lane = threadIdx.x & 31;
    for (int e = (blockIdx.x * blockDim.x + threadIdx.x) >> 5; e < g_ccnt; e += nwarp) {
        const int row = g_clist[e];
        float sc = NEG_BIG;
        if (lane < 4) {
            const float* a = A + (size_t)row * H_DIM;
            const float* w = W + (size_t)lane * H_DIM;
            float acc = 0.0f;
            for (int k = 0; k < H_DIM; k++) acc = fmaf(a[k], w[k], acc);
            const float x = acc + bias[lane];
            sc = gumbel_u32(rand32(kc0, kc1, (uint32_t)(row * 4 + lane))) +
                 __fdiv_rn(x, 1e-4f);
        }
        int bi = lane;
#pragma unroll
        for (int o = 1; o < 4; o <<= 1) {
            float os = __shfl_xor_sync(0xffffffffu, sc, o);
            int oi = __shfl_xor_sync(0xffffffffu, bi, o);
            if (os > sc || (os == sc && oi < bi)) { sc = os; bi = oi; }
        }
        if (lane == 0) {
            float2* o2 = (float2*)(out + (size_t)row * 10);
            o2[0] = make_float2(bi == 0 ? 1.f : 0.f, bi == 1 ? 1.f : 0.f);
            o2[1] = make_float2(bi == 2 ? 1.f : 0.f, bi == 3 ? 1.f : 0.f);
        }
    }
}

// ---------------- mix fixup: exact sequential recompute incl. mean/logstd ----------------
__global__ __launch_bounds__(64)
void mix_fixup(const float* __restrict__ A, const float* __restrict__ W,
               const float* __restrict__ bias, float* __restrict__ out,
               uint32_t km0, uint32_t km1, uint32_t kg0, uint32_t kg1) {
    __shared__ float sa[H_DIM];
    __shared__ float sx[50];
    for (int e = blockIdx.x; e < g_mcnt; e += gridDim.x) {
        const int gw = g_mlist[e];
        const int sbr = gw / 6;
        const int j = gw - sbr * 6;
        __syncthreads();
        {
            const float4* src = (const float4*)(A + (size_t)sbr * H_DIM);
            float4* dst = (float4*)sa;
            for (int i = threadIdx.x; i < H_DIM / 4; i += 64) dst[i] = src[i];
        }
        __syncthreads();
        const int c = threadIdx.x;
        if (c < 50) {
            const int col = 4 + j * 150 + c;
            const float* w = W + (size_t)col * H_DIM;
            float acc = 0.0f;
            for (int k = 0; k < H_DIM; k++) acc = fmaf(sa[k], w[k], acc);
            sx[c] = acc + bias[col];
        }
        __syncthreads();
        if (threadIdx.x == 0) {
            float m = sx[0];
            for (int i = 1; i < 50; i++) m = fmaxf(m, sx[i]);
            float s = 0.0f;
            for (int i = 0; i < 50; i++) s += expf(sx[i] - m);
            const float lse = logf(s) + m;
            float bsc = NEG_BIG; int bk = 0;
            const uint32_t eb = (uint32_t)gw * 50u;
            for (int i = 0; i < 50; i++) {
                const float g = gumbel_u32(rand32(km0, km1, eb + (uint32_t)i));
                const float sc = g + __fdiv_rn(sx[i] - lse, 1e-4f);
                if (sc > bsc) { bsc = sc; bk = i; }
            }
            const int cm = 4 + j * 150 + 50 + bk;
            const int cl = cm + 50;
            const float* wm = W + (size_t)cm * H_DIM;
            const float* wl = W + (size_t)cl * H_DIM;
            float am = 0.0f, al = 0.0f;
            for (int k = 0; k < H_DIM; k++) {
                am = fmaf(sa[k], wm[k], am);
                al = fmaf(sa[k], wl[k], al);
            }
            const float mean = am + bias[cm];
            const float lstd = al + bias[cl];
            const float n = normal_u32(rand32(kg0, kg1, (uint32_t)gw));
            out[(size_t)sbr * 10 + 4 + j] = mean + expf(lstd) * (n * 0.01f);
        }
    }
}

// ---------------- host threefry ----------------
static inline uint32_t h_rotl(uint32_t v, int r) { return (v << r) | (v >> (32 - r)); }
static void h_tf(uint32_t k0, uint32_t k1, uint32_t c0, uint32_t c1,
                 uint32_t* o0, uint32_t* o1) {
    uint32_t ks2 = k0 ^ k1 ^ 0x1BD11BDAu;
    uint32_t x0 = c0 + k0, x1 = c1 + k1;
    uint32_t ks[3] = {k0, k1, ks2};
    const int RA[4] = {13, 15, 26, 6};
    const int RB[4] = {17, 29, 16, 24};
    for (int blk = 0; blk < 5; blk++) {
        const int* rr = (blk & 1) ? RB : RA;
        for (int i = 0; i < 4; i++) { x0 += x1; x1 = h_rotl(x1, rr[i]); x1 ^= x0; }
        x0 += ks[(blk + 1) % 3];
        x1 += ks[(blk + 2) % 3] + (uint32_t)(blk + 1);
    }
    *o0 = x0; *o1 = x1;
}

extern "C" void kernel_launch(void* const* d_in, const int* in_sizes, int n_in,
                              void* d_out, int out_size) {
    const float* A = (const float*)d_in[0];
    const float* W = (const float*)d_in[1];
    const float* b = (const float*)d_in[2];
    float* out = (float*)d_out;

    uint32_t kc0, kc1, km0, km1, kg0, kg1;
    h_tf(0u, 42u, 0u, 0u, &kc0, &kc1);
    h_tf(0u, 42u, 0u, 1u, &km0, &km1);
    h_tf(0u, 42u, 0u, 2u, &kg0, &kg1);

    zero_counters<<<1, 1>>>();
    build_Wc<<<(NC * H_DIM / 4 + 255) / 256, 256>>>(W, b);
    gemm_kernel<<<dim3(NC / BN, M_DIM / BM), 256>>>(A);
    command_kernel<<<(M_DIM + 255) / 256, 256>>>(out);

    const int mwpb = 8;
    mixture_kernel<<<(NARG + mwpb - 1) / mwpb, mwpb * 32>>>();
    gather_kernel<<<M_DIM, 384>>>(A, W, b, out, kg0, kg1);

    cmd_fixup<<<1024, 256>>>(A, W, b, out, kc0, kc1);
    mix_fixup<<<8192, 64>>>(A, W, b, out, km0, km1, kg0, kg1);
}